// round 13
// baseline (speedup 1.0000x reference)
#include <cuda_runtime.h>
#include <cstdint>

// CoExCostVolume: cost[b,d,h,w] = sum_c x[b,c,h,w]*y[b,c,h,w-d], zero for w<d.
// B=8, C=96, H=128, W=416, D=49.
//
// One CTA per (b,h) row, 832 threads = 26 warps = 13 warp-pairs; pair g owns
// d in [4g, 4g+4) (g=12: d=48 only), lane index l (<52) owns w in [8l, 8l+8).
// d-tile 4 => 32 accumulators/thread => ~65 regs => 26 warps/SM (vs 14 at
// d-tile 7), the occupancy R12's profile said we were walled on.
// Because d0 is a multiple of 4, the window phase R=(w0+53-4g)&3 == 1 for ALL
// groups: a single accum code path, y window = 3 LDS.128 with immediate
// offsets f[1..11].
// XOR swizzle S(p)=p^((p>>3)&4): 16B-alignment preserving, conflict-free for
// lane-stride-8-float LDS.128; each 16B vector uses its own swizzled address.
// cp.async(8B) 3-buffer depth-2 pipeline, 6 chunks of 16 channels; staging is
// exactly 4 rows of 208 float2 per iteration (no index wrap, hoisted swizzles).

#define B_DIM 8
#define C_DIM 96
#define H_DIM 128
#define W_DIM 416
#define D_DIM 49
#define HW (H_DIM * W_DIM)

#define CC 16
#define NC 6
#define NBUF 3
#define PAD 56                 // y left pad (coords p = w + 56)
#define XSTRIDE 448
#define YSTRIDE 480            // max touched: SW(471)=467 < 480
#define XSZ (CC * XSTRIDE)
#define BUFSZ (XSZ + CC * YSTRIDE)
#define NTHREADS 832
#define SMEM_BYTES (NBUF * BUFSZ * 4)   // 178176

__device__ __forceinline__ int SW(int p) { return p ^ ((p >> 3) & 4); }

__device__ __forceinline__ void cp8(float* dst_smem, const float* src) {
    unsigned s = (unsigned)__cvta_generic_to_shared(dst_smem);
    asm volatile("cp.async.ca.shared.global [%0], [%1], 8;\n" ::"r"(s), "l"(src));
}

// One 16-channel chunk; phase R==1 for every group.
// acc(i,j) uses y float f[4 + j - i], i in [0,4), j in [0,8) -> f[1..11].
__device__ __forceinline__ void accum(const float* __restrict__ buf,
                                      int xo0, int xo1,
                                      const int* __restrict__ yo,
                                      float* __restrict__ acc) {
#pragma unroll 4
    for (int c = 0; c < CC; c++) {
        float4 xa = *(const float4*)(buf + xo0 + c * XSTRIDE);
        float4 xc = *(const float4*)(buf + xo1 + c * XSTRIDE);
        float xv[8] = {xa.x, xa.y, xa.z, xa.w, xc.x, xc.y, xc.z, xc.w};

        float f[12];
#pragma unroll
        for (int v = 0; v < 3; v++) {
            float4 q = *(const float4*)(buf + yo[v] + c * YSTRIDE);
            f[4 * v + 0] = q.x; f[4 * v + 1] = q.y;
            f[4 * v + 2] = q.z; f[4 * v + 3] = q.w;
        }

#pragma unroll
        for (int i = 0; i < 4; i++)
#pragma unroll
            for (int j = 0; j < 8; j++)
                acc[i * 8 + j] = fmaf(xv[j], f[4 + j - i], acc[i * 8 + j]);
    }
}

__global__ void __launch_bounds__(NTHREADS, 1)
coex_cost_kernel(const float* __restrict__ x,
                 const float* __restrict__ y,
                 float* __restrict__ out) {
    extern __shared__ float sm[];

    const int bid = blockIdx.x;
    const int b = bid >> 7;
    const int h = bid & 127;
    const int tid = threadIdx.x;
    const int wid = tid >> 5;               // 0..25
    const int lane = tid & 31;
    const int g = wid >> 1;                 // 0..12 d-group (warp-uniform)
    const int l = ((wid & 1) << 5) + lane;  // 0..63
    const bool active = (l < 52);
    const int d0 = 4 * g;                   // 0,4,...,48
    const int w0 = 8 * l;

    const long rowb = ((long)(b * C_DIM) * H_DIM + h) * W_DIM;

    // ---- zero y left-pad once (all buffers); SW maps each 8-block to itself
    // so raw fill of [0, PAD) covers the swizzled image. ----
    for (int i = tid; i < NBUF * CC * PAD; i += NTHREADS) {
        int buf = i / (CC * PAD);
        int rest = i - buf * (CC * PAD);
        int c = rest / PAD;
        int p = rest - c * PAD;
        sm[buf * BUFSZ + XSZ + c * YSTRIDE + p] = 0.0f;
    }

    // ---- per-thread addresses (window base qa = w0 + 52 - 4g, 16B aligned) ----
    const int w0c = active ? w0 : 0;
    const int qa = w0c + 52 - d0;           // >= 4, 4-aligned
    const int xo0 = SW(w0c);
    const int xo1 = SW(w0c + 4);            // own swizzle — NOT xo0+4
    int yo[3];
#pragma unroll
    for (int v = 0; v < 3; v++) yo[v] = XSZ + SW(qa + 4 * v);

    float acc[32];
#pragma unroll
    for (int i = 0; i < 32; i++) acc[i] = 0.0f;

    // ---- staging: 832 threads = exactly 4 rows of 208 float2 per pass ----
    const int c0 = tid / 208;               // 0..3
    const int p0 = tid - c0 * 208;          // float2 index in row
    const int wst = 2 * p0;
    const int sxo = SW(wst);                // hoisted swizzles (w fixed per thread)
    const int syo = SW(PAD + wst);
    auto stage = [&](int k) {
        float* bx = sm + (k % NBUF) * BUFSZ;
        float* by = bx + XSZ;
        const float* xg = x + rowb + (long)k * CC * HW + wst;
        const float* yg = y + rowb + (long)k * CC * HW + wst;
#pragma unroll
        for (int it = 0; it < 4; it++) {
            int c = c0 + 4 * it;
            cp8(bx + c * XSTRIDE + sxo, xg + (long)c * HW);
            cp8(by + c * YSTRIDE + syo, yg + (long)c * HW);
        }
    };

    stage(0); asm volatile("cp.async.commit_group;\n");
    stage(1); asm volatile("cp.async.commit_group;\n");

#pragma unroll 1
    for (int k = 0; k < NC; k++) {
        if (k < NC - 1) asm volatile("cp.async.wait_group 1;\n" ::: "memory");
        else            asm volatile("cp.async.wait_group 0;\n" ::: "memory");
        __syncthreads();

        if (k + 2 < NC) {
            stage(k + 2);
            asm volatile("cp.async.commit_group;\n");
        }

        const float* buf = sm + (k % NBUF) * BUFSZ;
        if (active) accum(buf, xo0, xo1, yo, acc);
    }

    // ---- stores: up to 4 d x 8 w per active thread ----
    if (active) {
#pragma unroll
        for (int i = 0; i < 4; i++) {
            const int d = d0 + i;
            if (d < D_DIM) {
                float* o = out + (((long)b * D_DIM + d) * H_DIM + h) * W_DIM + w0;
                *reinterpret_cast<float4*>(o) =
                    make_float4(acc[i * 8 + 0], acc[i * 8 + 1], acc[i * 8 + 2], acc[i * 8 + 3]);
                *reinterpret_cast<float4*>(o + 4) =
                    make_float4(acc[i * 8 + 4], acc[i * 8 + 5], acc[i * 8 + 6], acc[i * 8 + 7]);
            }
        }
    }
}

extern "C" void kernel_launch(void* const* d_in, const int* in_sizes, int n_in,
                              void* d_out, int out_size) {
    const float* x = (const float*)d_in[0];
    const float* y = (const float*)d_in[1];
    float* out = (float*)d_out;

    cudaFuncSetAttribute(coex_cost_kernel,
                         cudaFuncAttributeMaxDynamicSharedMemorySize, SMEM_BYTES);

    coex_cost_kernel<<<B_DIM * H_DIM, NTHREADS, SMEM_BYTES>>>(x, y, out);
}

// round 14
// speedup vs baseline: 1.2492x; 1.2492x over previous
#include <cuda_runtime.h>
#include <cstdint>

// CoExCostVolume: cost[b,d,h,w] = sum_c x[b,c,h,w]*y[b,c,h,w-d], zero for w<d.
// B=8, C=96, H=128, W=416, D=49.
//
// R12 frame (best, 197us): one CTA per (b,h) row, 448 threads = 7 warp-pairs;
// pair g owns d in [7g,7g+7), lane index l (<52) owns w in [8l,8l+8).
// XOR swizzle S(p)=p^((p>>3)&4), conflict-free lane-stride-8 LDS.128, scalar
// FFMA compute (56/channel), 4 accum<R> phase variants.
// R14 change: CC=24, NC=4, NBUF=2 — fewer barrier quanta, longer compute runs
// for deeper software pipelining; staging latency still covered depth-1.

#define B_DIM 8
#define C_DIM 96
#define H_DIM 128
#define W_DIM 416
#define D_DIM 49
#define HW (H_DIM * W_DIM)

#define CC 24
#define NC 4
#define NBUF 2
#define XSTRIDE 448
#define YSTRIDE 480
#define XSZ (CC * XSTRIDE)
#define BUFSZ (XSZ + CC * YSTRIDE)      // 22272 floats
#define NTHREADS 448
#define SMEM_BYTES (NBUF * BUFSZ * 4)   // 178176

__device__ __forceinline__ int SW(int p) { return p ^ ((p >> 3) & 4); }

__device__ __forceinline__ void cp8(float* dst_smem, const float* src) {
    unsigned s = (unsigned)__cvta_generic_to_shared(dst_smem);
    asm volatile("cp.async.ca.shared.global [%0], [%1], 8;\n" ::"r"(s), "l"(src));
}

// One 24-channel chunk. R = q0&3 (warp-uniform window phase).
// Window scalars occupy float offsets [R, R+13] of the 4*NV loaded floats.
template <int R>
__device__ __forceinline__ void accum(const float* __restrict__ buf,
                                      int xo0, int xo1,
                                      const int* __restrict__ yo,
                                      float* __restrict__ acc) {
    constexpr int NV = (R == 3) ? 5 : 4;
#pragma unroll 6
    for (int c = 0; c < CC; c++) {
        float4 xa = *(const float4*)(buf + xo0 + c * XSTRIDE);
        float4 xc = *(const float4*)(buf + xo1 + c * XSTRIDE);
        float xv[8] = {xa.x, xa.y, xa.z, xa.w, xc.x, xc.y, xc.z, xc.w};

        float f[4 * NV];
#pragma unroll
        for (int v = 0; v < NV; v++) {
            float4 q = *(const float4*)(buf + yo[v] + c * YSTRIDE);
            f[4 * v + 0] = q.x; f[4 * v + 1] = q.y;
            f[4 * v + 2] = q.z; f[4 * v + 3] = q.w;
        }

#pragma unroll
        for (int i = 0; i < 7; i++)
#pragma unroll
            for (int j = 0; j < 8; j++)
                acc[i * 8 + j] = fmaf(xv[j], f[R + j + 6 - i], acc[i * 8 + j]);
    }
}

__global__ void __launch_bounds__(NTHREADS, 1)
coex_cost_kernel(const float* __restrict__ x,
                 const float* __restrict__ y,
                 float* __restrict__ out) {
    extern __shared__ float sm[];

    const int bid = blockIdx.x;
    const int b = bid >> 7;
    const int h = bid & 127;
    const int tid = threadIdx.x;
    const int wid = tid >> 5;
    const int lane = tid & 31;
    const int g = wid >> 1;                 // 0..6 d-group (warp-uniform)
    const int l = ((wid & 1) << 5) + lane;  // 0..63
    const bool active = (l < 52);
    const int d0 = 7 * g;
    const int w0 = 8 * l;

    const long rowb = ((long)(b * C_DIM) * H_DIM + h) * W_DIM;

    // ---- zero y left-pad once (all buffers); SW is a bijection on [0,48) ----
    for (int i = tid; i < NBUF * CC * 48; i += NTHREADS) {
        int buf = i / (CC * 48);
        int rest = i - buf * (CC * 48);
        int c = rest / 48;
        int p = rest - c * 48;
        sm[buf * BUFSZ + XSZ + c * YSTRIDE + p] = 0.0f;
    }

    // ---- per-thread addresses ----
    const int w0c = active ? w0 : 0;
    const int q0c = active ? (w0 + 42 - d0) : 0;   // window base, >= 0
    const int R = q0c & 3;                          // warp-uniform
    const int qa = q0c - R;
    const int xo0 = SW(w0c);
    const int xo1 = SW(w0c + 4);                    // own swizzle — NOT xo0+4
    int yo[5];
#pragma unroll
    for (int v = 0; v < 5; v++) yo[v] = XSZ + SW(qa + 4 * v);

    float acc[56];
#pragma unroll
    for (int i = 0; i < 56; i++) acc[i] = 0.0f;

    // ---- staging: additive (c, p) advance, 8B cp.async for x and y ----
    const int c0 = tid / 208;            // 0..2
    const int p0 = tid - c0 * 208;       // float2 index within row
    auto stage = [&](int k) {
        float* bx = sm + (k & (NBUF - 1)) * BUFSZ;
        float* by = bx + XSZ;
        const float* xg = x + rowb + (long)k * CC * HW;
        const float* yg = y + rowb + (long)k * CC * HW;
        int c = c0, p = p0;
#pragma unroll 1
        for (int it = 0; it < 12; it++) {
            if (c < CC) {
                int w = 2 * p;
                long gsrc = (long)c * HW + w;
                cp8(bx + c * XSTRIDE + SW(w), xg + gsrc);
                cp8(by + c * YSTRIDE + SW(48 + w), yg + gsrc);
            }
            c += 2; p += 32;                 // +448 float2 = 2 rows + 32
            if (p >= 208) { p -= 208; c += 1; }
        }
    };

    stage(0); asm volatile("cp.async.commit_group;\n");

#pragma unroll 1
    for (int k = 0; k < NC; k++) {
        asm volatile("cp.async.wait_group 0;\n" ::: "memory");
        __syncthreads();

        if (k + 1 < NC) {
            stage(k + 1);
            asm volatile("cp.async.commit_group;\n");
        }

        const float* buf = sm + (k & (NBUF - 1)) * BUFSZ;
        if (active) {
            switch (R) {
                case 0: accum<0>(buf, xo0, xo1, yo, acc); break;
                case 1: accum<1>(buf, xo0, xo1, yo, acc); break;
                case 2: accum<2>(buf, xo0, xo1, yo, acc); break;
                default: accum<3>(buf, xo0, xo1, yo, acc); break;
            }
        }
        __syncthreads();
    }

    // ---- stores: 7 d x 8 w per active thread, two float4 per d ----
    if (active) {
#pragma unroll
        for (int i = 0; i < 7; i++) {
            const int d = d0 + i;
            float* o = out + (((long)b * D_DIM + d) * H_DIM + h) * W_DIM + w0;
            *reinterpret_cast<float4*>(o) =
                make_float4(acc[i * 8 + 0], acc[i * 8 + 1], acc[i * 8 + 2], acc[i * 8 + 3]);
            *reinterpret_cast<float4*>(o + 4) =
                make_float4(acc[i * 8 + 4], acc[i * 8 + 5], acc[i * 8 + 6], acc[i * 8 + 7]);
        }
    }
}

extern "C" void kernel_launch(void* const* d_in, const int* in_sizes, int n_in,
                              void* d_out, int out_size) {
    const float* x = (const float*)d_in[0];
    const float* y = (const float*)d_in[1];
    float* out = (float*)d_out;

    cudaFuncSetAttribute(coex_cost_kernel,
                         cudaFuncAttributeMaxDynamicSharedMemorySize, SMEM_BYTES);

    coex_cost_kernel<<<B_DIM * H_DIM, NTHREADS, SMEM_BYTES>>>(x, y, out);
}